// round 10
// baseline (speedup 1.0000x reference)
#include <cuda_runtime.h>
#include <cuda_bf16.h>

// Problem constants
#define BATCH   8
#define IN_P    16     // in_planes
#define REP_C   16     // PROD_DW / IN_PLANES
#define OUT_P   32     // out_planes
#define PV      256    // 32*32 pixels / 4 (float4 pixel-vecs)
#define C_X     256    // PROD_DW channels of x
#define C_OUT1  8192   // OUT_P * PROD_DW

#define OUT1_VECS ((size_t)BATCH * C_OUT1 * PV)   // 16777216 float4

// Block = (b, i, pixel-quarter): 512 blocks x 64 threads. Each thread owns one
// pixel-vec, loads its 16 rep-channels of x ONCE (x is read exactly once from
// L2/DRAM chip-wide -> minimum possible LTS traffic), computes gate bits for
// ALL 32 output channels (reference rounding: sequential sum of the PRODUCTS
// w*x_r over r=0..15), then streams 32x16 float4 stores.
__global__ __launch_bounds__(64) void qconv_pw_kernel(
    const float4* __restrict__ x,      // (B,256,1024) -> (B,256,256) float4
    const float4* __restrict__ x2,     // (B,16,1024)  -> (B,16,256)  float4
    const float*  __restrict__ w,      // (32,16)
    float4* __restrict__ out)          // out1 vecs then out2 vecs
{
    const int tid = threadIdx.x;       // 0..63
    const int blk = blockIdx.x;        // 0..511
    const int pq  = blk & 3;           // pixel quarter
    const int i   = (blk >> 2) & 15;   // in-plane
    const int b   = blk >> 6;          // batch
    const int p   = pq * 64 + tid;     // pixel-vec 0..255

    __shared__ float ws[OUT_P * IN_P];
    #pragma unroll
    for (int k = 0; k < 8; k++)
        ws[tid + k * 64] = w[tid + k * 64];
    __syncthreads();

    // Load the 16 rep-channels for this (b,i) pixel-vec; keep in registers.
    const float4* xc = x + ((size_t)b * C_X + (size_t)i * REP_C) * PV + p;
    float4 xr[REP_C];
    #pragma unroll
    for (int r = 0; r < REP_C; r++)
        xr[r] = __ldg(&xc[(size_t)r * PV]);

    // Phase 1: gate bits for all 32 o (one uint32 per pixel component).
    uint m_x = 0u, m_y = 0u, m_z = 0u, m_w = 0u;
    #pragma unroll
    for (int o = 0; o < OUT_P; o++) {
        const float wv = ws[o * IN_P + i];
        float tx = 0.f, ty = 0.f, tz = 0.f, tw = 0.f;
        #pragma unroll
        for (int r = 0; r < REP_C; r++) {
            tx += wv * xr[r].x;
            ty += wv * xr[r].y;
            tz += wv * xr[r].z;
            tw += wv * xr[r].w;
        }
        m_x |= (tx > 0.f ? 1u : 0u) << o;
        m_y |= (ty > 0.f ? 1u : 0u) << o;
        m_z |= (tz > 0.f ? 1u : 0u) << o;
        m_w |= (tw > 0.f ? 1u : 0u) << o;
    }

    // Phase 2: streaming-store sweep, 32 o x 16 r.
    float4* ob = out + ((size_t)b * C_OUT1 + (size_t)i * REP_C) * PV + p;
    #pragma unroll 4
    for (int o = 0; o < OUT_P; o++) {
        const float wv = ws[o * IN_P + i];
        const float gx = ((m_x >> o) & 1u) ? wv : 0.f;
        const float gy = ((m_y >> o) & 1u) ? wv : 0.f;
        const float gz = ((m_z >> o) & 1u) ? wv : 0.f;
        const float gw = ((m_w >> o) & 1u) ? wv : 0.f;

        float4* dst = ob + (size_t)o * (C_X * PV);
        #pragma unroll
        for (int r = 0; r < REP_C; r++) {
            float4 s;
            s.x = gx * xr[r].x;
            s.y = gy * xr[r].y;
            s.z = gz * xr[r].z;
            s.w = gw * xr[r].w;
            __stcs(&dst[(size_t)r * PV], s);   // streaming: never re-read
        }
    }

    // Dense 1x1 conv + ReLU path (tiny, 1 MB): i==0 blocks handle all 32 o
    // for their pixel quarter. Sequential ii matches the einsum rounding.
    if (i == 0) {
        const float4* x2b = x2 + (size_t)b * IN_P * PV + p;
        #pragma unroll 1
        for (int o = 0; o < OUT_P; o++) {
            float ax = 0.f, ay = 0.f, az = 0.f, aw = 0.f;
            #pragma unroll
            for (int ii = 0; ii < IN_P; ii++) {
                const float4 v = __ldg(&x2b[(size_t)ii * PV]);  // L1/L2 hits
                const float wv = ws[o * IN_P + ii];
                ax = fmaf(wv, v.x, ax);
                ay = fmaf(wv, v.y, ay);
                az = fmaf(wv, v.z, az);
                aw = fmaf(wv, v.w, aw);
            }
            float4 r;
            r.x = fmaxf(ax, 0.f);
            r.y = fmaxf(ay, 0.f);
            r.z = fmaxf(az, 0.f);
            r.w = fmaxf(aw, 0.f);
            out[OUT1_VECS + ((size_t)b * OUT_P + o) * PV + p] = r;
        }
    }
}

extern "C" void kernel_launch(void* const* d_in, const int* in_sizes, int n_in,
                              void* d_out, int out_size)
{
    const float4* x  = (const float4*)d_in[0];
    const float4* x2 = (const float4*)d_in[1];
    const float*  w  = (const float*) d_in[2];
    float4* out = (float4*)d_out;

    qconv_pw_kernel<<<BATCH * IN_P * 4, 64>>>(x, x2, w, out);
}

// round 11
// speedup vs baseline: 1.1788x; 1.1788x over previous
#include <cuda_runtime.h>
#include <cuda_bf16.h>

// Problem constants
#define BATCH   8
#define IN_P    16     // in_planes
#define REP_C   16     // PROD_DW / IN_PLANES
#define OUT_P   32     // out_planes
#define PV      256    // 32*32 pixels / 4 (float4 pixel-vecs)
#define C_X     256    // PROD_DW channels of x
#define C_OUT1  8192   // OUT_P * PROD_DW
#define O_PER_C 8      // o values per main block

#define OUT1_VECS ((size_t)BATCH * C_OUT1 * PV)   // 16777216 float4

// Main blocks (0..511): (b, i, o-chunk-of-8), 256 threads = 1 pixel-vec each.
// Load the 16 rep-channels of x ONCE into registers, compute 8 gate bits
// (reference rounding: sequential sum of the PRODUCTS w*x_r, r=0..15), then
// stream 8x16 perfectly-coalesced float4 stores. x L2 amplification = 4x
// (32 MB) vs 256 MB of mandatory writes.
// Tail blocks (512..519): one per batch, the tiny dense relu(out2) path —
// peeled out so the 512 main blocks are perfectly uniform.
__global__ __launch_bounds__(256) void qconv_pw_kernel(
    const float4* __restrict__ x,      // (B,256,1024) -> (B,256,256) float4
    const float4* __restrict__ x2,     // (B,16,1024)  -> (B,16,256)  float4
    const float*  __restrict__ w,      // (32,16)
    float4* __restrict__ out)          // out1 vecs then out2 vecs
{
    const int tid = threadIdx.x;
    const int blk = blockIdx.x;

    __shared__ float ws[OUT_P * IN_P];
    ws[tid] = w[tid];
    ws[tid + 256] = w[tid + 256];
    __syncthreads();

    if (blk >= BATCH * IN_P * 4) {
        // ---- out2 path: relu(einsum('bihw,oi->bohw')) for one batch ----
        const int b = blk - BATCH * IN_P * 4;
        const int p = tid;
        const float4* x2b = x2 + (size_t)b * IN_P * PV + p;

        float4 xv[IN_P];
        #pragma unroll
        for (int ii = 0; ii < IN_P; ii++)
            xv[ii] = __ldg(&x2b[(size_t)ii * PV]);

        #pragma unroll 4
        for (int o = 0; o < OUT_P; o++) {
            float ax = 0.f, ay = 0.f, az = 0.f, aw = 0.f;
            #pragma unroll
            for (int ii = 0; ii < IN_P; ii++) {   // sequential ii: einsum order
                const float wv = ws[o * IN_P + ii];
                ax = fmaf(wv, xv[ii].x, ax);
                ay = fmaf(wv, xv[ii].y, ay);
                az = fmaf(wv, xv[ii].z, az);
                aw = fmaf(wv, xv[ii].w, aw);
            }
            float4 r;
            r.x = fmaxf(ax, 0.f);
            r.y = fmaxf(ay, 0.f);
            r.z = fmaxf(az, 0.f);
            r.w = fmaxf(aw, 0.f);
            out[OUT1_VECS + ((size_t)b * OUT_P + o) * PV + p] = r;
        }
        return;
    }

    // ---- main out1 path ----
    const int oc = blk & 3;            // o-chunk (8 o each)
    const int i  = (blk >> 2) & 15;    // in-plane
    const int b  = blk >> 6;           // batch
    const int p  = tid;                // pixel-vec 0..255

    // Load the 16 rep-channels for this (b,i) pixel-vec; keep in registers.
    const float4* xc = x + ((size_t)b * C_X + (size_t)i * REP_C) * PV + p;
    float4 xr[REP_C];
    #pragma unroll
    for (int r = 0; r < REP_C; r++)
        xr[r] = __ldg(&xc[(size_t)r * PV]);

    // Phase 1: gate bits for the 8 o values (exact reference rounding:
    // sequential sum of the PRODUCTS w*x_r over r = 0..15).
    uint m_x = 0u, m_y = 0u, m_z = 0u, m_w = 0u;
    #pragma unroll
    for (int oo = 0; oo < O_PER_C; oo++) {
        const float wv = ws[(oc * O_PER_C + oo) * IN_P + i];
        float tx = 0.f, ty = 0.f, tz = 0.f, tw = 0.f;
        #pragma unroll
        for (int r = 0; r < REP_C; r++) {
            tx += wv * xr[r].x;
            ty += wv * xr[r].y;
            tz += wv * xr[r].z;
            tw += wv * xr[r].w;
        }
        m_x |= (tx > 0.f ? 1u : 0u) << oo;
        m_y |= (ty > 0.f ? 1u : 0u) << oo;
        m_z |= (tz > 0.f ? 1u : 0u) << oo;
        m_w |= (tw > 0.f ? 1u : 0u) << oo;
    }

    // Phase 2: streaming-store sweep, 8 o x 16 r.
    float4* ob = out + ((size_t)b * C_OUT1 + (size_t)i * REP_C) * PV + p;
    #pragma unroll
    for (int oo = 0; oo < O_PER_C; oo++) {
        const int o = oc * O_PER_C + oo;
        const float wv = ws[o * IN_P + i];
        const float gx = ((m_x >> oo) & 1u) ? wv : 0.f;
        const float gy = ((m_y >> oo) & 1u) ? wv : 0.f;
        const float gz = ((m_z >> oo) & 1u) ? wv : 0.f;
        const float gw = ((m_w >> oo) & 1u) ? wv : 0.f;

        float4* dst = ob + (size_t)o * (C_X * PV);
        #pragma unroll
        for (int r = 0; r < REP_C; r++) {
            float4 s;
            s.x = gx * xr[r].x;
            s.y = gy * xr[r].y;
            s.z = gz * xr[r].z;
            s.w = gw * xr[r].w;
            __stcs(&dst[(size_t)r * PV], s);   // streaming: never re-read
        }
    }
}

extern "C" void kernel_launch(void* const* d_in, const int* in_sizes, int n_in,
                              void* d_out, int out_size)
{
    const float4* x  = (const float4*)d_in[0];
    const float4* x2 = (const float4*)d_in[1];
    const float*  w  = (const float*) d_in[2];
    float4* out = (float4*)d_out;

    qconv_pw_kernel<<<BATCH * IN_P * 4 + BATCH, 256>>>(x, x2, w, out);
}